// round 1
// baseline (speedup 1.0000x reference)
#include <cuda_runtime.h>

// SinusoidalPositionalEncoding: out[b,s,d] = x[b,s,d] + pe[s,d]
//   pe[s, 2j]   = sin(s * omega[j])
//   pe[s, 2j+1] = cos(s * omega[j])
// Shapes fixed by the problem: x [8, 4096, 1024] fp32, omega [512] fp32.
//
// Strategy:
//  - HBM-bound streaming kernel (268 MB compulsory traffic -> ~40 us floor).
//  - pe is batch-independent: compute once per (s, d) and apply to all 8 batches.
//  - Each thread owns one float4 column (2 omega pairs) and 8 consecutive s-rows.
//    4 accurate sincosf calls per thread (base angle + per-step rotation), then
//    advance with the angle-addition recurrence (4 FMAs/pair/step). This keeps
//    total accurate-trig work ~14 us, hidden under the memory stream, while
//    avoiding MUFU.SIN range-reduction error at args up to ~4095.

#define PE_B 8
#define PE_S 4096
#define PE_D 1024
#define PE_Q (PE_D / 4)        // 256 float4 columns per row
#define SROWS 8                // s-rows per thread via rotation recurrence

__global__ __launch_bounds__(PE_Q) void sinpe_kernel(
    const float4* __restrict__ x,
    const float*  __restrict__ omega,
    float4*       __restrict__ out)
{
    const int q  = threadIdx.x;            // float4 column: covers pairs 2q, 2q+1
    const int s0 = blockIdx.x * SROWS;

    const float w0 = __ldg(&omega[2 * q]);
    const float w1 = __ldg(&omega[2 * q + 1]);

    // Base angles at s0 (accurate path), plus one-step rotation constants.
    float sn0, cs0, sn1, cs1;
    float ds0, dc0, ds1, dc1;
    sincosf((float)s0 * w0, &sn0, &cs0);
    sincosf((float)s0 * w1, &sn1, &cs1);
    sincosf(w0, &ds0, &dc0);
    sincosf(w1, &ds1, &dc1);

    const long bstride = (long)PE_S * PE_Q;   // float4 elements per batch slice
    long base = (long)s0 * PE_Q + q;

    #pragma unroll
    for (int r = 0; r < SROWS; ++r) {
        const float pex = sn0, pey = cs0, pez = sn1, pew = cs1;

        #pragma unroll
        for (int b = 0; b < PE_B; ++b) {
            const long idx = base + (long)b * bstride;
            float4 v = x[idx];
            v.x += pex; v.y += pey; v.z += pez; v.w += pew;
            out[idx] = v;
        }
        base += PE_Q;  // next s-row

        // Rotate both pairs to angle (s+1)*w:
        //   sin(a+w) = sin(a)cos(w) + cos(a)sin(w)
        //   cos(a+w) = cos(a)cos(w) - sin(a)sin(w)
        const float ns0 = fmaf(sn0, dc0,  cs0 * ds0);
        const float nc0 = fmaf(cs0, dc0, -sn0 * ds0);
        const float ns1 = fmaf(sn1, dc1,  cs1 * ds1);
        const float nc1 = fmaf(cs1, dc1, -sn1 * ds1);
        sn0 = ns0; cs0 = nc0; sn1 = ns1; cs1 = nc1;
    }
}

extern "C" void kernel_launch(void* const* d_in, const int* in_sizes, int n_in,
                              void* d_out, int out_size)
{
    const float4* x     = (const float4*)d_in[0];
    const float*  omega = (const float*)d_in[1];
    float4*       out   = (float4*)d_out;

    // 512 blocks x 256 threads: each block covers 8 s-rows across full D and all batches.
    sinpe_kernel<<<PE_S / SROWS, PE_Q>>>(x, omega, out);
}

// round 2
// speedup vs baseline: 1.1250x; 1.1250x over previous
#include <cuda_runtime.h>

// SinusoidalPositionalEncoding: out[b,s,d] = x[b,s,d] + pe[s,d]
//   pe[s, 2j]   = sin(s * omega[j]),  pe[s, 2j+1] = cos(s * omega[j])
// Shapes: x [8, 4096, 1024] fp32, omega [512] fp32. Output fp32, same shape.
//
// R2 design (post-mortem of R1):
//  - R1 (512 big blocks, 8-row recurrence) hit only 59.5% DRAM: the 1.15-wave
//    grid left a 68-block tail that couldn't keep enough bytes in flight.
//  - Trig is per-WARP cheap: with batch-reuse (x8) direct sincosf per (s, q)
//    is only ~2.6M warp-instructions chip-wide (~2-3us) — fully hidden.
//  - So: one block per s-row (4096 blocks x 256 threads), thread = one float4
//    column, 2 sincosf, then 8 unrolled batch load/add/store pairs.
//    ~40 regs -> ~6 CTAs/SM; 4.6 waves with a fat (544-block) last wave keeps
//    HBM saturated through the drain.

#define PE_B 8
#define PE_S 4096
#define PE_D 1024
#define PE_Q (PE_D / 4)        // 256 float4 columns per row

__global__ __launch_bounds__(PE_Q) void sinpe_kernel(
    const float4* __restrict__ x,
    const float*  __restrict__ omega,
    float4*       __restrict__ out)
{
    const int q = threadIdx.x;     // float4 column -> omega pairs 2q, 2q+1
    const int s = blockIdx.x;      // sequence position

    const float w0 = __ldg(&omega[2 * q]);
    const float w1 = __ldg(&omega[2 * q + 1]);

    const float fs = (float)s;
    float sn0, cs0, sn1, cs1;
    sincosf(fs * w0, &sn0, &cs0);   // accurate path; args up to ~4095 rad
    sincosf(fs * w1, &sn1, &cs1);

    const long bstride = (long)PE_S * PE_Q;       // float4 elems per batch slice
    const long base    = (long)s * PE_Q + q;

    // 8 independent 128-bit loads in flight, then 8 stores.
    float4 v[PE_B];
    #pragma unroll
    for (int b = 0; b < PE_B; ++b)
        v[b] = x[base + (long)b * bstride];

    #pragma unroll
    for (int b = 0; b < PE_B; ++b) {
        v[b].x += sn0; v[b].y += cs0; v[b].z += sn1; v[b].w += cs1;
        out[base + (long)b * bstride] = v[b];
    }
}

extern "C" void kernel_launch(void* const* d_in, const int* in_sizes, int n_in,
                              void* d_out, int out_size)
{
    const float4* x     = (const float4*)d_in[0];
    const float*  omega = (const float*)d_in[1];
    float4*       out   = (float4*)d_out;

    sinpe_kernel<<<PE_S, PE_Q>>>(x, omega, out);
}